// round 14
// baseline (speedup 1.0000x reference)
#include <cuda_runtime.h>
#include <math.h>

// Hawkes univariate NLL — single launch, 2 blocks (one per batch row).
// Sorted x =>  S[j] = exp(-w x_j) * P[j] - dup(j),
//              P[j] = exclusive prefix of exp(w x_i).
// R13 skeleton + two more post-barrier chain cuts:
//  * ONE fused logf per thread: prod of all 8 A_k (range [3.9e-3, 5.9e30],
//    safe fp32; error << budget).
//  * duplicate-run chain computed PRE-barrier (lanes 1-31 via shfl); lane-0
//    cross-warp boundary handled by a rare post-barrier fix-up.
//  * Abase_k = mu*e_k + aw*p_k and sumx pre-barrier; post-barrier adds Q only.
//  * single-atom 64-bit publish tail; epilogue const on publisher block.

#define HK_N       8192
#define HK_THREADS 1024
#define HK_VPT     8
#define HK_T       1.0f
#define HK_REG     0.01f

__device__ volatile unsigned long long g_word;   // 0 = empty; {1<<32 | bits}

__device__ __forceinline__ float fast_rcp(float a) {
    float r;
    asm("rcp.approx.f32 %0, %1;" : "=f"(r) : "f"(a));
    return r;
}

__global__ __launch_bounds__(HK_THREADS)
void hawkes_kernel(const float* __restrict__ x,
                   const float* __restrict__ mu_p,
                   const float* __restrict__ alpha_p,
                   const float* __restrict__ w_p,
                   float* __restrict__ out) {
    __shared__ float warp_scan[32];
    __shared__ float warp_last[32];
    __shared__ float red[32];

    const int b   = blockIdx.x;
    const int tid = threadIdx.x;
    const unsigned lane = tid & 31u;
    const unsigned wid  = tid >> 5;

    const float mu    = *mu_p;
    const float alpha = *alpha_p;
    const float w     = *w_p;
    const float aw    = alpha * w;
    const float emwT  = __expf(-w * HK_T);

    // Epilogue constant on the PUBLISHER block (slack path).
    float base_const = 0.0f;
    if (b == 1 && tid == 0)
        base_const = mu * HK_T
                   + HK_REG * (-__logf(mu) - __logf(alpha) - __logf(w));

    const float* __restrict__ xr = x + (size_t)b * HK_N;
    const int base = tid * HK_VPT;

    // ---- load 8 contiguous values (2x float4, coalesced) ----
    float xv[HK_VPT];
    {
        const float4 a0 = *reinterpret_cast<const float4*>(xr + base);
        const float4 a1 = *reinterpret_cast<const float4*>(xr + base + 4);
        xv[0]=a0.x; xv[1]=a0.y; xv[2]=a0.z; xv[3]=a0.w;
        xv[4]=a1.x; xv[5]=a1.y; xv[6]=a1.z; xv[7]=a1.w;
    }

    // ---- e = exp(w*x): 8 independent MUFU exps ----
    float e[HK_VPT];
    #pragma unroll
    for (int k = 0; k < HK_VPT; k++) e[k] = __expf(w * xv[k]);

    // depth-3 tree for thread total + exclusive prefixes
    const float t01 = e[0] + e[1], t23 = e[2] + e[3];
    const float t45 = e[4] + e[5], t67 = e[6] + e[7];
    const float t03 = t01 + t23,   t47 = t45 + t67;
    const float run = t03 + t47;

    float p[HK_VPT];
    p[0] = 0.0f;        p[1] = e[0];
    p[2] = t01;         p[3] = t01 + e[2];
    p[4] = t03;         p[5] = t03 + e[4];
    p[6] = t03 + t45;   p[7] = t03 + t45 + e[6];

    // ---- PRE-BARRIER: Abase_k, sumx tree ----
    float Abase[HK_VPT];
    #pragma unroll
    for (int k = 0; k < HK_VPT; k++)
        Abase[k] = fmaf(mu, e[k], aw * p[k]);
    const float sx01 = xv[0]+xv[1], sx23 = xv[2]+xv[3];
    const float sx45 = xv[4]+xv[5], sx67 = xv[6]+xv[7];
    const float sumx_all = (sx01 + sx23) + (sx45 + sx67);

    // ---- PRE-BARRIER: duplicate-run counts assuming a clean lane-0
    //      cross-warp boundary; lanes 1-31 use the shfl'd prev value. ----
    const float prev_in_warp = __shfl_up_sync(0xffffffffu, xv[HK_VPT - 1], 1);
    float c[HK_VPT];
    {
        c[0] = (lane > 0u && xv[0] == prev_in_warp) ? 1.0f : 0.0f;
        if (c[0] != 0.0f) {
            // within-warp boundary duplicate: count the actual run (rare)
            int pq = base - 1;
            float c0 = 0.0f;
            while (pq >= 0 && xr[pq] == xv[0]) { c0 += 1.0f; --pq; }
            c[0] = c0;
        }
        #pragma unroll
        for (int k = 1; k < HK_VPT; k++)
            c[k] = (xv[k] == xv[k - 1]) ? c[k - 1] + 1.0f : 0.0f;
    }
    bool any_dup = false;
    #pragma unroll
    for (int k = 0; k < HK_VPT; k++) any_dup |= (c[k] != 0.0f);

    // ---- warp inclusive scan of thread totals ----
    float v = run;
    #pragma unroll
    for (int off = 1; off < 32; off <<= 1) {
        float n = __shfl_up_sync(0xffffffffu, v, off);
        if (lane >= (unsigned)off) v += n;
    }
    if (lane == 31u) {
        warp_scan[wid] = v;
        warp_last[wid] = xv[HK_VPT - 1];
    }
    __syncthreads();

    // ---- every warp redundantly scans the 32 warp totals (one barrier) ----
    float wt = warp_scan[lane];
    #pragma unroll
    for (int off = 1; off < 32; off <<= 1) {
        float n = __shfl_up_sync(0xffffffffu, wt, off);
        if (lane >= (unsigned)off) wt += n;
    }
    const float warp_excl = (wid > 0)
        ? __shfl_sync(0xffffffffu, wt, wid - 1) : 0.0f;
    const float row_total = __shfl_sync(0xffffffffu, wt, 31);

    const float thread_excl = (v - run) + warp_excl;
    const float Q = aw * thread_excl;             // only scan-dep factor

    // ---- rare fix-up: lane-0 cross-warp duplicate boundary ----
    if (lane == 0u && wid > 0 && xv[0] == warp_last[wid - 1]) {
        int pq = base - 1;
        float c0 = 0.0f;
        while (pq >= 0 && xr[pq] == xv[0]) { c0 += 1.0f; --pq; }
        c[0] = c0;
        #pragma unroll
        for (int k = 1; k < HK_VPT; k++)
            c[k] = (xv[k] == xv[k - 1]) ? c[k - 1] + 1.0f : 0.0f;
        any_dup = true;
    }

    // ---- POST-BARRIER common path: A_k = Abase_k + Q; ONE fused logf ----
    float acc = 0.0f, sumx = sumx_all;
    float A[HK_VPT];
    if (!any_dup) {
        #pragma unroll
        for (int k = 0; k < HK_VPT; k++) A[k] = Abase[k] + Q;
    } else {
        #pragma unroll
        for (int k = 0; k < HK_VPT; k++) {
            if (c[k] == 0.0f) {
                A[k] = Abase[k] + Q;
            } else {
                A[k] = 1.0f;
                sumx -= xv[k];
                const float P = thread_excl + p[k];
                float S = P * fast_rcp(e[k]) - c[k];
                if (S < 0.0f) S = 0.0f;
                acc -= __logf(fmaf(aw, S, mu));
            }
        }
    }
    const float prod = ((A[0]*A[1]) * (A[2]*A[3]))
                     * ((A[4]*A[5]) * (A[6]*A[7]));
    acc -= __logf(prod);                          // single MUFU log
    acc = fmaf(w, sumx, acc);

    // closed-form neg for the whole row, added once
    if (tid == 0)
        acc += alpha * ((float)HK_N - emwT * row_total);

    // ---- block reduction ----
    #pragma unroll
    for (int off = 16; off > 0; off >>= 1)
        acc += __shfl_down_sync(0xffffffffu, acc, off);
    if (lane == 0u) red[wid] = acc;
    __syncthreads();
    if (wid == 0) {
        float r = red[lane];
        #pragma unroll
        for (int off = 16; off > 0; off >>= 1)
            r += __shfl_down_sync(0xffffffffu, r, off);
        if (lane == 0u) {
            if (b == 1) {
                // one 8-byte atom: value + readiness travel together.
                const float payload = r + base_const;
                g_word = (1ULL << 32)
                       | (unsigned long long)__float_as_uint(payload);
            } else {
                unsigned long long m;
                do { m = g_word; } while ((m >> 32) == 0ULL);
                const float r1 = __uint_as_float((unsigned int)m);
                out[0] = r + r1;                 // fixed order: deterministic
                g_word = 0ULL;                   // reset for next replay
            }
        }
    }
}

extern "C" void kernel_launch(void* const* d_in, const int* in_sizes, int n_in,
                              void* d_out, int out_size) {
    const float* x     = (const float*)d_in[0];
    const float* mu    = (const float*)d_in[1];
    const float* alpha = (const float*)d_in[2];
    const float* w     = (const float*)d_in[3];
    float* out = (float*)d_out;

    const int total = in_sizes[0];
    const int B = total / HK_N;                 // B=2, N=8192 fixed
    hawkes_kernel<<<B, HK_THREADS>>>(x, mu, alpha, w, out);
}

// round 15
// speedup vs baseline: 1.1208x; 1.1208x over previous
#include <cuda_runtime.h>
#include <math.h>

// Hawkes univariate NLL — single launch, 2 blocks (one per batch row).
// Sorted x =>  S[j] = exp(-w x_j) * P[j] - dup(j),
//              P[j] = exclusive prefix of exp(w x_i).
// R13 skeleton (best measured: 6.05us ncu, 49 regs) + ONE register-neutral
// change: single fused logf (product of all 8 A_k; range [3.9e-3, 5.9e30],
// safe fp32). Duplicate logic stays post-barrier (R14's pre-barrier variant
// blew regs 49->63 and regressed).
//  * Abase_k = mu*e_k + aw*p_k and sumx pre-barrier; post-barrier adds Q.
//  * single-atom 64-bit publish tail; epilogue const on publisher block.
//  * neg term closed form from the scan row total.

#define HK_N       8192
#define HK_THREADS 1024
#define HK_VPT     8
#define HK_T       1.0f
#define HK_REG     0.01f

__device__ volatile unsigned long long g_word;   // 0 = empty; {1<<32 | bits}

__device__ __forceinline__ float fast_rcp(float a) {
    float r;
    asm("rcp.approx.f32 %0, %1;" : "=f"(r) : "f"(a));
    return r;
}

__global__ __launch_bounds__(HK_THREADS)
void hawkes_kernel(const float* __restrict__ x,
                   const float* __restrict__ mu_p,
                   const float* __restrict__ alpha_p,
                   const float* __restrict__ w_p,
                   float* __restrict__ out) {
    __shared__ float warp_scan[32];
    __shared__ float warp_last[32];
    __shared__ float red[32];

    const int b   = blockIdx.x;
    const int tid = threadIdx.x;
    const unsigned lane = tid & 31u;
    const unsigned wid  = tid >> 5;

    const float mu    = *mu_p;
    const float alpha = *alpha_p;
    const float w     = *w_p;
    const float aw    = alpha * w;
    const float emwT  = __expf(-w * HK_T);

    // Epilogue constant on the PUBLISHER block (slack path).
    float base_const = 0.0f;
    if (b == 1 && tid == 0)
        base_const = mu * HK_T
                   + HK_REG * (-__logf(mu) - __logf(alpha) - __logf(w));

    const float* __restrict__ xr = x + (size_t)b * HK_N;
    const int base = tid * HK_VPT;

    // ---- load 8 contiguous values (2x float4, coalesced) ----
    float xv[HK_VPT];
    {
        const float4 a0 = *reinterpret_cast<const float4*>(xr + base);
        const float4 a1 = *reinterpret_cast<const float4*>(xr + base + 4);
        xv[0]=a0.x; xv[1]=a0.y; xv[2]=a0.z; xv[3]=a0.w;
        xv[4]=a1.x; xv[5]=a1.y; xv[6]=a1.z; xv[7]=a1.w;
    }

    // ---- e = exp(w*x): 8 independent MUFU exps ----
    float e[HK_VPT];
    #pragma unroll
    for (int k = 0; k < HK_VPT; k++) e[k] = __expf(w * xv[k]);

    // depth-3 tree for thread total + exclusive prefixes
    const float t01 = e[0] + e[1], t23 = e[2] + e[3];
    const float t45 = e[4] + e[5], t67 = e[6] + e[7];
    const float t03 = t01 + t23,   t47 = t45 + t67;
    const float run = t03 + t47;

    float p[HK_VPT];
    p[0] = 0.0f;        p[1] = e[0];
    p[2] = t01;         p[3] = t01 + e[2];
    p[4] = t03;         p[5] = t03 + e[4];
    p[6] = t03 + t45;   p[7] = t03 + t45 + e[6];

    // ---- PRE-BARRIER: Abase_k = mu*e_k + aw*p_k  and  sumx (tree) ----
    float Abase[HK_VPT];
    #pragma unroll
    for (int k = 0; k < HK_VPT; k++)
        Abase[k] = fmaf(mu, e[k], aw * p[k]);
    const float sx01 = xv[0]+xv[1], sx23 = xv[2]+xv[3];
    const float sx45 = xv[4]+xv[5], sx67 = xv[6]+xv[7];
    const float sumx_all = (sx01 + sx23) + (sx45 + sx67);

    // ---- warp inclusive scan of thread totals ----
    float v = run;
    #pragma unroll
    for (int off = 1; off < 32; off <<= 1) {
        float n = __shfl_up_sync(0xffffffffu, v, off);
        if (lane >= (unsigned)off) v += n;
    }
    const float prev_in_warp = __shfl_up_sync(0xffffffffu, xv[HK_VPT - 1], 1);
    if (lane == 31u) {
        warp_scan[wid] = v;
        warp_last[wid] = xv[HK_VPT - 1];
    }
    __syncthreads();

    // ---- every warp redundantly scans the 32 warp totals (one barrier) ----
    float wt = warp_scan[lane];
    #pragma unroll
    for (int off = 1; off < 32; off <<= 1) {
        float n = __shfl_up_sync(0xffffffffu, wt, off);
        if (lane >= (unsigned)off) wt += n;
    }
    const float warp_excl = (wid > 0)
        ? __shfl_sync(0xffffffffu, wt, wid - 1) : 0.0f;
    const float row_total = __shfl_sync(0xffffffffu, wt, 31);

    const float thread_excl = (v - run) + warp_excl;
    const float Q = aw * thread_excl;             // the only scan-dep factor

    float prev_last = -1.0f;                      // x >= 0: never equal
    if (tid > 0)
        prev_last = (lane == 0u) ? warp_last[wid - 1] : prev_in_warp;

    // ---- duplicate-run counts (register chain; global walk only if a run
    //      crosses a thread boundary — astronomically rare) ----
    float c[HK_VPT];
    {
        float c0 = 0.0f;
        if (xv[0] == prev_last) {
            int pq = base - 1;
            while (pq >= 0 && xr[pq] == xv[0]) { c0 += 1.0f; --pq; }
        }
        c[0] = c0;
        #pragma unroll
        for (int k = 1; k < HK_VPT; k++)
            c[k] = (xv[k] == xv[k - 1]) ? c[k - 1] + 1.0f : 0.0f;
    }

    // ---- POST-BARRIER: A_k = Abase_k + Q; ONE fused logf ----
    float acc = 0.0f, sumx = sumx_all;
    float A[HK_VPT];
    #pragma unroll
    for (int k = 0; k < HK_VPT; k++) {
        if (c[k] == 0.0f) {
            A[k] = Abase[k] + Q;
        } else {
            A[k] = 1.0f;
            sumx -= xv[k];                        // remove from the -w*x fold
            const float P = thread_excl + p[k];
            float S = P * fast_rcp(e[k]) - c[k];
            if (S < 0.0f) S = 0.0f;
            acc -= __logf(fmaf(aw, S, mu));
        }
    }
    const float prod = ((A[0]*A[1]) * (A[2]*A[3]))
                     * ((A[4]*A[5]) * (A[6]*A[7]));
    acc -= __logf(prod);                          // single MUFU log
    acc = fmaf(w, sumx, acc);

    // closed-form neg for the whole row, added once
    if (tid == 0)
        acc += alpha * ((float)HK_N - emwT * row_total);

    // ---- block reduction ----
    #pragma unroll
    for (int off = 16; off > 0; off >>= 1)
        acc += __shfl_down_sync(0xffffffffu, acc, off);
    if (lane == 0u) red[wid] = acc;
    __syncthreads();
    if (wid == 0) {
        float r = red[lane];
        #pragma unroll
        for (int off = 16; off > 0; off >>= 1)
            r += __shfl_down_sync(0xffffffffu, r, off);
        if (lane == 0u) {
            if (b == 1) {
                // one 8-byte atom: value + readiness travel together.
                const float payload = r + base_const;
                g_word = (1ULL << 32)
                       | (unsigned long long)__float_as_uint(payload);
            } else {
                unsigned long long m;
                do { m = g_word; } while ((m >> 32) == 0ULL);
                const float r1 = __uint_as_float((unsigned int)m);
                out[0] = r + r1;                 // fixed order: deterministic
                g_word = 0ULL;                   // reset for next replay
            }
        }
    }
}

extern "C" void kernel_launch(void* const* d_in, const int* in_sizes, int n_in,
                              void* d_out, int out_size) {
    const float* x     = (const float*)d_in[0];
    const float* mu    = (const float*)d_in[1];
    const float* alpha = (const float*)d_in[2];
    const float* w     = (const float*)d_in[3];
    float* out = (float*)d_out;

    const int total = in_sizes[0];
    const int B = total / HK_N;                 // B=2, N=8192 fixed
    hawkes_kernel<<<B, HK_THREADS>>>(x, mu, alpha, w, out);
}